// round 9
// baseline (speedup 1.0000x reference)
#include <cuda_runtime.h>
#include <math.h>

#define EMB    4096
#define DIM    4096
#define TPREV  8192
#define TTOT   (TPREV + 1)     // 8193
#define NCHUNK 64
#define CHUNK  (EMB / NCHUNK)  // 64
#define TPAD   8224            // padded stride for partials (mult of 32)

// Scratch (device globals — no allocation allowed)
__device__ __align__(16) float g_q[DIM];
__device__ __align__(16) float g_k[DIM];
__device__ __align__(16) float g_v[DIM];
__device__ __align__(16) float g_part[NCHUNK * TPAD];
__device__ __align__(16) float g_a[TTOT + 3];

__device__ __forceinline__ float warp_red(float v) {
#pragma unroll
    for (int off = 16; off; off >>= 1)
        v += __shfl_xor_sync(0xffffffffu, v, off);
    return v;
}

// ---------------------------------------------------------------------------
// Kernel 1: q/k/v = W{q,k,v} @ x. Single wave: 512 blocks of 256 (4096 warps),
// each warp computes ONE row of each of Wq, Wk, Wv (3 sequential iterations).
// Inner body = R4's proven 4 x (8 W + 8 x) independent LDG.128 batches.
// ---------------------------------------------------------------------------
__global__ void __launch_bounds__(256, 4)
qkv_kernel(const float* __restrict__ x,
           const float* __restrict__ Wq,
           const float* __restrict__ Wk,
           const float* __restrict__ Wv) {
    int warp = threadIdx.x >> 5;
    int lane = threadIdx.x & 31;
    int row  = blockIdx.x * 8 + warp;         // 0..4095

    const float4* xv = reinterpret_cast<const float4*>(x);

#pragma unroll
    for (int which = 0; which < 3; which++) {
        const float* W = (which == 0) ? Wq : (which == 1) ? Wk : Wv;
        const float4* wr = reinterpret_cast<const float4*>(W) + (size_t)row * (EMB / 4);

        float acc = 0.0f;
#pragma unroll
        for (int b = 0; b < 4; b++) {         // 4 batches of 8 float4 per lane
            float4 w[8], xx[8];
#pragma unroll
            for (int j = 0; j < 8; j++) {
                int i = lane + (b * 8 + j) * 32;
                w[j]  = wr[i];
                xx[j] = __ldg(&xv[i]);
            }
#pragma unroll
            for (int j = 0; j < 8; j++)
                acc += w[j].x * xx[j].x + w[j].y * xx[j].y
                     + w[j].z * xx[j].z + w[j].w * xx[j].w;
        }
        acc = warp_red(acc);

        if (lane == 0) {
            float* dst = (which == 0) ? g_q : (which == 1) ? g_k : g_v;
            dst[row] = acc;
        }
    }
}

// ---------------------------------------------------------------------------
// Kernel 2: partial scores. Single wave: grid (8,32) = 256 blocks of 256;
// each block processes chunk c = blockIdx.y and c + 32.
// Thread owns one float4 along t; unroll 16 front-batches independent LDG.128.
// Deterministic partials. t=8192 tail handled in kernel 3.
// ---------------------------------------------------------------------------
__global__ void __launch_bounds__(256, 4)
score_partial_kernel(const float* __restrict__ Kc) {
    __shared__ float sq[CHUNK];
    int t4 = blockIdx.x * blockDim.x + threadIdx.x;   // 0..2047

#pragma unroll
    for (int it = 0; it < 2; it++) {
        int c  = blockIdx.y + it * 32;
        int d0 = c * CHUNK;
        if (it) __syncthreads();              // protect sq reuse
        if (threadIdx.x < CHUNK)
            sq[threadIdx.x] = g_q[d0 + threadIdx.x];
        __syncthreads();

        const float4* col = reinterpret_cast<const float4*>(Kc) +
                            (size_t)d0 * (TPREV / 4) + t4;

        float4 acc = make_float4(0.f, 0.f, 0.f, 0.f);
#pragma unroll 16
        for (int d = 0; d < CHUNK; d++) {
            float4 kk = col[(size_t)d * (TPREV / 4)];
            float  s  = sq[d];
            acc.x += s * kk.x; acc.y += s * kk.y;
            acc.z += s * kk.z; acc.w += s * kk.w;
        }
        reinterpret_cast<float4*>(g_part + c * TPAD)[t4] = acc;
    }
}

// ---------------------------------------------------------------------------
// Kernel 3: reduce partials -> sigmoid scores. 33 blocks of 256:
// blocks 0..31 reduce over 64 chunks; block 32 computes the t=8192 tail.
// ---------------------------------------------------------------------------
__global__ void sigmoid_kernel() {
    if (blockIdx.x < 32) {
        int t = blockIdx.x * 256 + threadIdx.x;
        float s = 0.0f;
#pragma unroll
        for (int c = 0; c < NCHUNK; c++)
            s += g_part[c * TPAD + t];
        s *= 0.015625f;  // 1/sqrt(4096)
        g_a[t] = 1.0f / (1.0f + expf(-s));
    } else {
        __shared__ float red[256];
        float s = 0.0f;
#pragma unroll
        for (int j = 0; j < 16; j++) {
            int d = threadIdx.x + 256 * j;
            s += g_q[d] * g_k[d];
        }
        red[threadIdx.x] = s;
        __syncthreads();
#pragma unroll
        for (int w = 128; w >= 1; w >>= 1) {
            if (threadIdx.x < w) red[threadIdx.x] += red[threadIdx.x + w];
            __syncthreads();
        }
        if (threadIdx.x == 0) {
            float v = red[0] * 0.015625f;
            g_a[TPREV] = 1.0f / (1.0f + expf(-v));
        }
    }
}

// ---------------------------------------------------------------------------
// Kernel 4: z[d] = V_cache[d,:] . a[0:T] + v[d]*a[T].
// Single wave: 256 blocks of 256 (2048 warps); each warp does 2 rows
// (row and row + 2048). Inner body = R4's 8 x (8 V + 8 a) batches.
// ---------------------------------------------------------------------------
__global__ void __launch_bounds__(256, 4)
out_kernel(const float* __restrict__ Vc, float* __restrict__ out) {
    int warp = threadIdx.x >> 5;
    int lane = threadIdx.x & 31;
    const float4* av = reinterpret_cast<const float4*>(g_a);

#pragma unroll
    for (int it = 0; it < 2; it++) {
        int row = it * 2048 + blockIdx.x * 8 + warp;
        const float4* vr = reinterpret_cast<const float4*>(Vc) + (size_t)row * (TPREV / 4);

        float acc = 0.0f;
#pragma unroll
        for (int b = 0; b < 8; b++) {         // 8 batches of 8 float4 per lane
            float4 v[8], a[8];
#pragma unroll
            for (int j = 0; j < 8; j++) {
                int i = lane + (b * 8 + j) * 32;
                v[j] = vr[i];
                a[j] = __ldg(&av[i]);
            }
#pragma unroll
            for (int j = 0; j < 8; j++)
                acc += v[j].x * a[j].x + v[j].y * a[j].y
                     + v[j].z * a[j].z + v[j].w * a[j].w;
        }
        acc = warp_red(acc);

        if (lane == 0)
            out[row] = acc + g_v[row] * g_a[TPREV];
    }
}

// ---------------------------------------------------------------------------
extern "C" void kernel_launch(void* const* d_in, const int* in_sizes, int n_in,
                              void* d_out, int out_size) {
    const float* x  = (const float*)d_in[0];
    const float* Wq = (const float*)d_in[1];
    const float* Wk = (const float*)d_in[2];
    const float* Wv = (const float*)d_in[3];
    const float* Kc = (const float*)d_in[4];
    const float* Vc = (const float*)d_in[5];
    float* out = (float*)d_out;

    qkv_kernel<<<512, 256>>>(x, Wq, Wk, Wv);

    dim3 sg(TPREV / (256 * 4), NCHUNK / 2);      // (8, 32)
    score_partial_kernel<<<sg, 256>>>(Kc);

    sigmoid_kernel<<<33, 256>>>();

    out_kernel<<<256, 256>>>(Vc, out);
}

// round 11
// speedup vs baseline: 1.3347x; 1.3347x over previous
#include <cuda_runtime.h>
#include <math.h>

#define EMB    4096
#define DIM    4096
#define TPREV  8192
#define TTOT   (TPREV + 1)     // 8193
#define NCHUNK 64
#define CHUNK  (EMB / NCHUNK)  // 64
#define TPAD   8224            // padded stride for partials (mult of 32)

// Scratch (device globals — no allocation allowed)
__device__ __align__(16) float g_q[DIM];
__device__ __align__(16) float g_k[DIM];
__device__ __align__(16) float g_v[DIM];
__device__ __align__(16) float g_part[NCHUNK * TPAD];
__device__ __align__(16) float g_a[TTOT + 3];

__device__ __forceinline__ float warp_red(float v) {
#pragma unroll
    for (int off = 16; off; off >>= 1)
        v += __shfl_xor_sync(0xffffffffu, v, off);
    return v;
}

// ---------------------------------------------------------------------------
// Kernel 1: q/k/v = W{q,k,v} @ x — ONE warp per output row. 4 batches of
// 8 front-grouped streaming W loads (__ldcs) + 8 L1 x loads.
// 12288 warps -> 1536 blocks of 256.
// ---------------------------------------------------------------------------
__global__ void __launch_bounds__(256, 4)
qkv_kernel(const float* __restrict__ x,
           const float* __restrict__ Wq,
           const float* __restrict__ Wk,
           const float* __restrict__ Wv) {
    int gw   = (blockIdx.x * blockDim.x + threadIdx.x) >> 5;
    int lane = threadIdx.x & 31;
    int which = gw >> 12;
    int row   = gw & (DIM - 1);

    const float* W = (which == 0) ? Wq : (which == 1) ? Wk : Wv;
    const float4* wr = reinterpret_cast<const float4*>(W) + (size_t)row * (EMB / 4);
    const float4* xv = reinterpret_cast<const float4*>(x);

    float acc = 0.0f;
#pragma unroll
    for (int b = 0; b < 4; b++) {            // 4 batches of 8 float4 per lane
        float4 w[8], xx[8];
#pragma unroll
        for (int j = 0; j < 8; j++)          // DRAM loads first (front-batched)
            w[j] = __ldcs(&wr[lane + (b * 8 + j) * 32]);
#pragma unroll
        for (int j = 0; j < 8; j++)          // L1-resident x loads after
            xx[j] = __ldg(&xv[lane + (b * 8 + j) * 32]);
#pragma unroll
        for (int j = 0; j < 8; j++)
            acc += w[j].x * xx[j].x + w[j].y * xx[j].y
                 + w[j].z * xx[j].z + w[j].w * xx[j].w;
    }
    acc = warp_red(acc);

    if (lane == 0) {
        float* dst = (which == 0) ? g_q : (which == 1) ? g_k : g_v;
        dst[row] = acc;
    }
}

// ---------------------------------------------------------------------------
// Kernel 2: partial scores. Grid (8, 64), block 256 -> 4096 warps.
// Thread owns one float4 along t, chunk of 64 d; unroll 16 front-batches
// independent streaming LDG.128. Deterministic partials. Tail in kernel 3.
// ---------------------------------------------------------------------------
__global__ void __launch_bounds__(256, 4)
score_partial_kernel(const float* __restrict__ Kc) {
    __shared__ float sq[CHUNK];
    int c  = blockIdx.y;
    int d0 = c * CHUNK;
    if (threadIdx.x < CHUNK)
        sq[threadIdx.x] = g_q[d0 + threadIdx.x];
    __syncthreads();

    int t4 = blockIdx.x * blockDim.x + threadIdx.x;   // 0..2047
    const float4* col = reinterpret_cast<const float4*>(Kc) +
                        (size_t)d0 * (TPREV / 4) + t4;

    float4 acc = make_float4(0.f, 0.f, 0.f, 0.f);
#pragma unroll 16
    for (int d = 0; d < CHUNK; d++) {
        float4 kk = __ldcs(&col[(size_t)d * (TPREV / 4)]);
        float  s  = sq[d];
        acc.x += s * kk.x; acc.y += s * kk.y;
        acc.z += s * kk.z; acc.w += s * kk.w;
    }
    reinterpret_cast<float4*>(g_part + c * TPAD)[t4] = acc;
}

// ---------------------------------------------------------------------------
// Kernel 3: reduce partials -> sigmoid scores. 33 blocks of 256:
// blocks 0..31 reduce over 64 chunks; block 32 computes the t=8192 tail.
// ---------------------------------------------------------------------------
__global__ void sigmoid_kernel() {
    if (blockIdx.x < 32) {
        int t = blockIdx.x * 256 + threadIdx.x;
        float s = 0.0f;
#pragma unroll
        for (int c = 0; c < NCHUNK; c++)
            s += g_part[c * TPAD + t];
        s *= 0.015625f;  // 1/sqrt(4096)
        g_a[t] = 1.0f / (1.0f + expf(-s));
    } else {
        __shared__ float red[256];
        float s = 0.0f;
#pragma unroll
        for (int j = 0; j < 16; j++) {
            int d = threadIdx.x + 256 * j;
            s += g_q[d] * g_k[d];
        }
        red[threadIdx.x] = s;
        __syncthreads();
#pragma unroll
        for (int w = 128; w >= 1; w >>= 1) {
            if (threadIdx.x < w) red[threadIdx.x] += red[threadIdx.x + w];
            __syncthreads();
        }
        if (threadIdx.x == 0) {
            float v = red[0] * 0.015625f;
            g_a[TPREV] = 1.0f / (1.0f + expf(-v));
        }
    }
}

// ---------------------------------------------------------------------------
// Kernel 4: z[d] = V_cache[d,:] . a[0:T] + v[d]*a[T].
// ONE warp per row; 8 batches of 8 front-grouped streaming V loads (__ldcs)
// + 8 L1 a loads. 4096 warps -> 512 blocks of 256.
// ---------------------------------------------------------------------------
__global__ void __launch_bounds__(256, 4)
out_kernel(const float* __restrict__ Vc, float* __restrict__ out) {
    int warp = threadIdx.x >> 5;
    int lane = threadIdx.x & 31;
    int row  = blockIdx.x * 8 + warp;

    const float4* vr = reinterpret_cast<const float4*>(Vc) + (size_t)row * (TPREV / 4);
    const float4* av = reinterpret_cast<const float4*>(g_a);

    float acc = 0.0f;
#pragma unroll
    for (int b = 0; b < 8; b++) {            // 8 batches of 8 float4 per lane
        float4 v[8], a[8];
#pragma unroll
        for (int j = 0; j < 8; j++)          // DRAM loads first (front-batched)
            v[j] = __ldcs(&vr[lane + (b * 8 + j) * 32]);
#pragma unroll
        for (int j = 0; j < 8; j++)          // L1-resident a loads after
            a[j] = __ldg(&av[lane + (b * 8 + j) * 32]);
#pragma unroll
        for (int j = 0; j < 8; j++)
            acc += v[j].x * a[j].x + v[j].y * a[j].y
                 + v[j].z * a[j].z + v[j].w * a[j].w;
    }
    acc = warp_red(acc);

    if (lane == 0)
        out[row] = acc + g_v[row] * g_a[TPREV];
}

// ---------------------------------------------------------------------------
extern "C" void kernel_launch(void* const* d_in, const int* in_sizes, int n_in,
                              void* d_out, int out_size) {
    const float* x  = (const float*)d_in[0];
    const float* Wq = (const float*)d_in[1];
    const float* Wk = (const float*)d_in[2];
    const float* Wv = (const float*)d_in[3];
    const float* Kc = (const float*)d_in[4];
    const float* Vc = (const float*)d_in[5];
    float* out = (float*)d_out;

    qkv_kernel<<<(3 * DIM) / 8, 256>>>(x, Wq, Wk, Wv);

    dim3 sg(TPREV / (256 * 4), NCHUNK);          // (8, 64)
    score_partial_kernel<<<sg, 256>>>(Kc);

    sigmoid_kernel<<<33, 256>>>();

    out_kernel<<<DIM / 8, 256>>>(Vc, out);
}